// round 4
// baseline (speedup 1.0000x reference)
#include <cuda_runtime.h>
#include <cuda_bf16.h>
#include <cstdint>

// Problem constants
#define BC      16            // B*C = 8*2
#define LL      2048          // sequence length
#define TSZ     17            // filter size
#define PAD     8             // TSZ/2

// xf stored TRANSPOSED: g_xf[bc][t][l]  (l contiguous)
__device__ float g_xf[BC * TSZ * LL];

// ---------------- f32x2 helpers (sm_103a packed fp32) ----------------
typedef double f32x2;

__device__ __forceinline__ f32x2 pack2(float lo, float hi) {
    f32x2 r;
    asm("mov.b64 %0, {%1, %2};" : "=d"(r) : "f"(lo), "f"(hi));
    return r;
}
__device__ __forceinline__ void ffma2(f32x2& d, f32x2 a, f32x2 b) {
    asm("fma.rn.f32x2 %0, %1, %2, %0;" : "+d"(d) : "d"(a), "d"(b));
}
__device__ __forceinline__ void unpack2(f32x2 v, float& lo, float& hi) {
    asm("mov.b64 {%0, %1}, %2;" : "=f"(lo), "=f"(hi) : "d"(v));
}

// ---------------- Kernel 0: xf[bc][t][l] = sum_s x[l+s-8] * filt[c][s][t] ----------------
__global__ void build_xf_kernel(const float* __restrict__ x,
                                const float* __restrict__ filt) {
    __shared__ float sf[TSZ * TSZ];
    int row = blockIdx.x * 256 + threadIdx.x;   // 0 .. BC*LL-1
    int bc = row >> 11;
    int l  = row & (LL - 1);
    int c  = bc & 1;

    for (int i = threadIdx.x; i < TSZ * TSZ; i += 256)
        sf[i] = filt[c * TSZ * TSZ + i];
    __syncthreads();

    float acc[TSZ];
#pragma unroll
    for (int t = 0; t < TSZ; t++) acc[t] = 0.0f;

    const float* xr = x + bc * LL;
#pragma unroll
    for (int s = 0; s < TSZ; s++) {
        int idx = l + s - PAD;
        float xv = (idx >= 0 && idx < LL) ? xr[idx] : 0.0f;
#pragma unroll
        for (int t = 0; t < TSZ; t++)
            acc[t] += xv * sf[s * TSZ + t];
    }

#pragma unroll
    for (int t = 0; t < TSZ; t++)
        g_xf[(bc * TSZ + t) * LL + l] = acc[t];   // transposed, coalesced
}

// ---------------- Kernel 1: main outer product ----------------
// out[bc][l][m] = sum_t xf[bc][t][l] * x[m+t-8]
// CTA tile: TL=64 (l) x TM=128 (m), 256 threads = 32(tx:m-groups) x 8(ty:l-groups)
// thread tile: 8 rows x 4 cols; acc paired over ROWS -> acc[4 rowpairs][4 m]
// 17-tap loop split into two phases so live broadcast-pair count stays <= 13
// (26 regs) and ptxas keeps them in registers (R2 failure: 24 live pairs got
// rematerialized from smem into the inner loop).
#define TL 64
#define TM 128

__global__ void __launch_bounds__(256, 2)
filter_main_kernel(const float* __restrict__ x, float* __restrict__ out) {
    __shared__ float sxf[TSZ][TL];        // xf tile, t-major
    __shared__ float sx[TM + 2 * PAD];    // x window for this m tile (144)

    const int bc = blockIdx.z;
    const int l0 = blockIdx.y * TL;
    const int m0 = blockIdx.x * TM;
    const int tid = threadIdx.x;
    const int tx = tid & 31;              // m group (warp-contiguous -> coalesced stores)
    const int ty = tid >> 5;              // l group (one ty per warp)
    const int lg = ty * 8;                // local row base (8 rows per thread)

    // ---- cooperative smem fill ----
    for (int i = tid; i < TSZ * TL; i += 256) {
        int t = i >> 6;                   // /64
        int j = i & 63;
        sxf[t][j] = g_xf[(bc * TSZ + t) * LL + l0 + j];
    }
    if (tid < TM + 2 * PAD) {
        int idx = m0 + tid - PAD;
        sx[tid] = (idx >= 0 && idx < LL) ? x[bc * LL + idx] : 0.0f;
    }
    __syncthreads();

    const int sxbase = tx * 4;            // sx[sxbase + j + t] = x[m0+tx*4+j+t-8]

    // ---- accumulators: acc[rp][j], rp -> rows (lg+2rp, lg+2rp+1) ----
    f32x2 acc[4][4];
#pragma unroll
    for (int rp = 0; rp < 4; rp++)
#pragma unroll
        for (int j = 0; j < 4; j++) acc[rp][j] = 0.0;

    // ================= Phase A: taps 0..7, needs bb[0..11] =================
    {
        f32x2 bb[12];
#pragma unroll
        for (int k = 0; k < 12; k++) {
            float s = sx[sxbase + k];
            bb[k] = pack2(s, s);
        }
#pragma unroll
        for (int t = 0; t < 8; t++) {
            float4 av0 = *reinterpret_cast<const float4*>(&sxf[t][lg]);
            float4 av1 = *reinterpret_cast<const float4*>(&sxf[t][lg + 4]);
            f32x2 ap[4];
            ap[0] = pack2(av0.x, av0.y);
            ap[1] = pack2(av0.z, av0.w);
            ap[2] = pack2(av1.x, av1.y);
            ap[3] = pack2(av1.z, av1.w);
#pragma unroll
            for (int rp = 0; rp < 4; rp++)
#pragma unroll
                for (int j = 0; j < 4; j++)
                    ffma2(acc[rp][j], ap[rp], bb[j + t]);
        }
    }

    // ================= Phase B: taps 8..16, needs bb[8..20] =================
    {
        f32x2 bb[13];
#pragma unroll
        for (int k = 0; k < 13; k++) {
            float s = sx[sxbase + 8 + k];
            bb[k] = pack2(s, s);
        }
#pragma unroll
        for (int t = 8; t < TSZ; t++) {
            float4 av0 = *reinterpret_cast<const float4*>(&sxf[t][lg]);
            float4 av1 = *reinterpret_cast<const float4*>(&sxf[t][lg + 4]);
            f32x2 ap[4];
            ap[0] = pack2(av0.x, av0.y);
            ap[1] = pack2(av0.z, av0.w);
            ap[2] = pack2(av1.x, av1.y);
            ap[3] = pack2(av1.z, av1.w);
#pragma unroll
            for (int rp = 0; rp < 4; rp++)
#pragma unroll
                for (int j = 0; j < 4; j++)
                    ffma2(acc[rp][j], ap[rp], bb[j + t - 8]);
        }
    }

    // ---- store: 8 rows x 4 cols, 1x STG.128 per row, fully coalesced ----
    const int mg = m0 + tx * 4;
    float* base = out + ((size_t)(bc * LL + l0 + lg)) * LL + mg;
#pragma unroll
    for (int rp = 0; rp < 4; rp++) {
        float e0[4], e1[4];
#pragma unroll
        for (int j = 0; j < 4; j++) unpack2(acc[rp][j], e0[j], e1[j]);
        *reinterpret_cast<float4*>(base + (size_t)(2 * rp) * LL) =
            make_float4(e0[0], e0[1], e0[2], e0[3]);
        *reinterpret_cast<float4*>(base + (size_t)(2 * rp + 1) * LL) =
            make_float4(e1[0], e1[1], e1[2], e1[3]);
    }
}

extern "C" void kernel_launch(void* const* d_in, const int* in_sizes, int n_in,
                              void* d_out, int out_size) {
    const float* x    = (const float*)d_in[0];   // [8,2,2048]
    const float* filt = (const float*)d_in[1];   // [1,2,17,17]
    float* out = (float*)d_out;                  // [8,2,2048,2048]

    build_xf_kernel<<<(BC * LL) / 256, 256>>>(x, filt);

    dim3 grid(LL / TM, LL / TL, BC);
    filter_main_kernel<<<grid, 256>>>(x, out);
}

// round 6
// speedup vs baseline: 1.5147x; 1.5147x over previous
#include <cuda_runtime.h>
#include <cuda_bf16.h>
#include <cstdint>

// Problem constants
#define BC      16            // B*C = 8*2
#define LL      2048
#define TSZ     17
#define PAD     8
#define KPAD    24            // taps padded to 24 (3 x k8 MMA steps; taps 17..23 zero)

// tf32 hi/lo planes of xf: [bc][l][KPAD], k-contiguous
__device__ float g_xf_hi[BC * LL * KPAD];
__device__ float g_xf_lo[BC * LL * KPAD];

__device__ __forceinline__ float to_tf32(float v) {
    uint32_t b;
    asm("cvt.rna.tf32.f32 %0, %1;" : "=r"(b) : "f"(v));
    return __uint_as_float(b);
}

// m16n8k8 tf32 MMA (sm_80+ baseline; valid on plain sm_103 target)
__device__ __forceinline__ void mma_tf32(float* c,
                                         uint32_t a0, uint32_t a1, uint32_t a2, uint32_t a3,
                                         uint32_t b0, uint32_t b1) {
    asm volatile(
        "mma.sync.aligned.m16n8k8.row.col.f32.tf32.tf32.f32 "
        "{%0,%1,%2,%3}, {%4,%5,%6,%7}, {%8,%9}, {%0,%1,%2,%3};"
        : "+f"(c[0]), "+f"(c[1]), "+f"(c[2]), "+f"(c[3])
        : "r"(a0), "r"(a1), "r"(a2), "r"(a3), "r"(b0), "r"(b1));
}

// ============ Kernel 0: xf[bc][l][t] = sum_s x[l+s-8]*filt[c][s][t], tf32 hi/lo split ============
__global__ void build_xf_kernel(const float* __restrict__ x,
                                const float* __restrict__ filt) {
    __shared__ float sf[TSZ * TSZ];
    int row = blockIdx.x * 256 + threadIdx.x;
    int bc = row >> 11;
    int l  = row & (LL - 1);
    int c  = bc & 1;

    for (int i = threadIdx.x; i < TSZ * TSZ; i += 256)
        sf[i] = filt[c * TSZ * TSZ + i];
    __syncthreads();

    float acc[TSZ];
#pragma unroll
    for (int t = 0; t < TSZ; t++) acc[t] = 0.0f;

    const float* xr = x + bc * LL;
#pragma unroll
    for (int s = 0; s < TSZ; s++) {
        int idx = l + s - PAD;
        float xv = (idx >= 0 && idx < LL) ? xr[idx] : 0.0f;
#pragma unroll
        for (int t = 0; t < TSZ; t++)
            acc[t] += xv * sf[s * TSZ + t];
    }

    float* oh = g_xf_hi + (size_t)(bc * LL + l) * KPAD;
    float* ol = g_xf_lo + (size_t)(bc * LL + l) * KPAD;
#pragma unroll
    for (int t = 0; t < TSZ; t++) {
        float hi = to_tf32(acc[t]);
        float lo = to_tf32(acc[t] - hi);
        oh[t] = hi;
        ol[t] = lo;
    }
#pragma unroll
    for (int t = TSZ; t < KPAD; t++) { oh[t] = 0.0f; ol[t] = 0.0f; }
}

// ============ Kernel 1: mma.sync tf32 GEMM ============
// D[128(l),128(m)] = A[128,24] * B[24,128],  B(k,n) = win[n+k] (never materialized)
// 8 warps: wy(2) x wx(4); warp tile 64(l) x 32(m) = 4 Mfrags x 4 Nfrags.
// A smem row stride 28 floats: 16B-aligned float4 fills AND conflict-free
// fragment reads (g*28 mod 32 distinct across the 8 lane-groups).
#define ASTRIDE 28
#define WINLEN  152

__global__ void __launch_bounds__(256)
filter_mma_kernel(const float* __restrict__ x, float* __restrict__ out) {
    __shared__ float As_hi[128 * ASTRIDE];
    __shared__ float As_lo[128 * ASTRIDE];
    __shared__ float win_h[WINLEN];
    __shared__ float win_l[WINLEN];

    const int tid = threadIdx.x;
    const int wid = tid >> 5;
    const int lane = tid & 31;
    const int g   = lane >> 2;    // groupID 0..7
    const int tig = lane & 3;     // thread-in-group 0..3
    const int wy = wid >> 2;      // 0..1  (l)
    const int wx = wid & 3;       // 0..3  (m)

    const int bc = blockIdx.z;
    const int l0 = blockIdx.y * 128;
    const int m0 = blockIdx.x * 128;

    // ---- x window hi/lo: win[i] = x[bc][m0 + i - 8] ----
    if (tid < WINLEN) {
        int gi = m0 + tid - PAD;
        float v = (gi >= 0 && gi < LL) ? x[bc * LL + gi] : 0.0f;
        float hi = to_tf32(v);
        win_h[tid] = hi;
        win_l[tid] = to_tf32(v - hi);
    }

    // ---- A fill: [128][24] row-major gmem -> smem stride 28, float4 all the way ----
    {
        const float4* gh = reinterpret_cast<const float4*>(g_xf_hi + (size_t)(bc * LL + l0) * KPAD);
        const float4* gl = reinterpret_cast<const float4*>(g_xf_lo + (size_t)(bc * LL + l0) * KPAD);
#pragma unroll
        for (int it = 0; it < 3; it++) {
            int f4 = it * 256 + tid;          // 0..767
            int row = f4 / 6, q = f4 % 6;
            float4 vh = gh[f4];
            float4 vl = gl[f4];
            *reinterpret_cast<float4*>(&As_hi[row * ASTRIDE + q * 4]) = vh;
            *reinterpret_cast<float4*>(&As_lo[row * ASTRIDE + q * 4]) = vl;
        }
    }
    __syncthreads();

    // ---- accumulators ----
    float acc[4][4][4];
#pragma unroll
    for (int mf = 0; mf < 4; mf++)
#pragma unroll
        for (int nf = 0; nf < 4; nf++)
#pragma unroll
            for (int j = 0; j < 4; j++) acc[mf][nf][j] = 0.0f;

    const int nbase = wx * 32 + g;            // B fragment col base
    const int rbase = wy * 64 + g;            // A fragment row base

    // ---- 3 passes (AhBh, AhBl, AlBh) x 3 k-steps x 16 MMAs ----
#pragma unroll
    for (int p = 0; p < 3; p++) {
        const float* Ap = (p == 2) ? As_lo : As_hi;
        const float* wp = (p == 1) ? win_l : win_h;
#pragma unroll
        for (int kt = 0; kt < 3; kt++) {
            const int kb = kt * 8 + tig;
            uint32_t b0[4], b1[4];
#pragma unroll
            for (int nf = 0; nf < 4; nf++) {
                b0[nf] = __float_as_uint(wp[nbase + nf * 8 + kb]);
                b1[nf] = __float_as_uint(wp[nbase + nf * 8 + kb + 4]);
            }
#pragma unroll
            for (int mf = 0; mf < 4; mf++) {
                const float* ar = Ap + (rbase + mf * 16) * ASTRIDE + kb;
                uint32_t a0 = __float_as_uint(ar[0]);
                uint32_t a1 = __float_as_uint(ar[8 * ASTRIDE]);
                uint32_t a2 = __float_as_uint(ar[4]);
                uint32_t a3 = __float_as_uint(ar[8 * ASTRIDE + 4]);
#pragma unroll
                for (int nf = 0; nf < 4; nf++)
                    mma_tf32(acc[mf][nf], a0, a1, a2, a3, b0[nf], b1[nf]);
            }
        }
    }

    // ---- store: fragment-layout st.v2 (each lane-quad covers 32B of a row) ----
#pragma unroll
    for (int mf = 0; mf < 4; mf++) {
        int row = l0 + rbase + mf * 16;
#pragma unroll
        for (int nf = 0; nf < 4; nf++) {
            int col = m0 + wx * 32 + nf * 8 + 2 * tig;
            float* p0 = out + (size_t)(bc * LL + row) * LL + col;
            float* p1 = p0 + (size_t)8 * LL;
            *reinterpret_cast<float2*>(p0) = make_float2(acc[mf][nf][0], acc[mf][nf][1]);
            *reinterpret_cast<float2*>(p1) = make_float2(acc[mf][nf][2], acc[mf][nf][3]);
        }
    }
}

extern "C" void kernel_launch(void* const* d_in, const int* in_sizes, int n_in,
                              void* d_out, int out_size) {
    const float* x    = (const float*)d_in[0];   // [8,2,2048]
    const float* filt = (const float*)d_in[1];   // [1,2,17,17]
    float* out = (float*)d_out;                  // [8,2,2048,2048]

    build_xf_kernel<<<(BC * LL) / 256, 256>>>(x, filt);

    dim3 grid(LL / 128, LL / 128, BC);
    filter_mma_kernel<<<grid, 256>>>(x, out);
}

// round 7
// speedup vs baseline: 1.5200x; 1.0035x over previous
#include <cuda_runtime.h>
#include <cuda_bf16.h>
#include <cstdint>

// Problem constants
#define BC      16            // B*C = 8*2
#define LL      2048
#define TSZ     17
#define PAD     8
#define KPAD    16            // MMA covers taps 0..15; tap 16 handled exactly in fp32

// tf32 hi/lo planes of xf (taps 0..15): [bc][l][16], k-contiguous
__device__ float g_xf_hi[BC * LL * KPAD];
__device__ float g_xf_lo[BC * LL * KPAD];
// tap 16 of xf, full fp32
__device__ float g_xf16[BC * LL];

__device__ __forceinline__ float to_tf32(float v) {
    uint32_t b;
    asm("cvt.rna.tf32.f32 %0, %1;" : "=r"(b) : "f"(v));
    return __uint_as_float(b);
}

// m16n8k8 tf32 MMA (sm_80+ baseline; valid on plain sm_103 target)
__device__ __forceinline__ void mma_tf32(float* c,
                                         uint32_t a0, uint32_t a1, uint32_t a2, uint32_t a3,
                                         uint32_t b0, uint32_t b1) {
    asm volatile(
        "mma.sync.aligned.m16n8k8.row.col.f32.tf32.tf32.f32 "
        "{%0,%1,%2,%3}, {%4,%5,%6,%7}, {%8,%9}, {%0,%1,%2,%3};"
        : "+f"(c[0]), "+f"(c[1]), "+f"(c[2]), "+f"(c[3])
        : "r"(a0), "r"(a1), "r"(a2), "r"(a3), "r"(b0), "r"(b1));
}

// ============ Kernel 0: xf[bc][l][t] = sum_s x[l+s-8]*filt[c][s][t] ============
__global__ void build_xf_kernel(const float* __restrict__ x,
                                const float* __restrict__ filt) {
    __shared__ float sf[TSZ * TSZ];
    int row = blockIdx.x * 256 + threadIdx.x;
    int bc = row >> 11;
    int l  = row & (LL - 1);
    int c  = bc & 1;

    for (int i = threadIdx.x; i < TSZ * TSZ; i += 256)
        sf[i] = filt[c * TSZ * TSZ + i];
    __syncthreads();

    float acc[TSZ];
#pragma unroll
    for (int t = 0; t < TSZ; t++) acc[t] = 0.0f;

    const float* xr = x + bc * LL;
#pragma unroll
    for (int s = 0; s < TSZ; s++) {
        int idx = l + s - PAD;
        float xv = (idx >= 0 && idx < LL) ? xr[idx] : 0.0f;
#pragma unroll
        for (int t = 0; t < TSZ; t++)
            acc[t] += xv * sf[s * TSZ + t];
    }

    // taps 0..15 -> tf32 hi/lo planes (float4 stores)
    float4* oh = reinterpret_cast<float4*>(g_xf_hi) + (size_t)(bc * LL + l) * 4;
    float4* ol = reinterpret_cast<float4*>(g_xf_lo) + (size_t)(bc * LL + l) * 4;
#pragma unroll
    for (int q = 0; q < 4; q++) {
        float h0 = to_tf32(acc[4 * q + 0]);
        float h1 = to_tf32(acc[4 * q + 1]);
        float h2 = to_tf32(acc[4 * q + 2]);
        float h3 = to_tf32(acc[4 * q + 3]);
        oh[q] = make_float4(h0, h1, h2, h3);
        ol[q] = make_float4(to_tf32(acc[4 * q + 0] - h0), to_tf32(acc[4 * q + 1] - h1),
                            to_tf32(acc[4 * q + 2] - h2), to_tf32(acc[4 * q + 3] - h3));
    }
    g_xf16[bc * LL + l] = acc[16];      // tap 16, full precision
}

// ============ Kernel 1: mma.sync tf32 GEMM + exact tap-16 rank-1 update ============
// D[128(l),128(m)] = A[128,16]*B[16,128] (3xTF32) + xf16[l] * x[m+8] (fp32)
// B(k,n) = win[n+k], never materialized (read from window smem, hoisted to regs).
// 8 warps: wy(4, l) x wx(2, m); warp tile 32(l) x 64(m) = 2 mf x 8 nf fragments.
#define ASTRIDE 20            // A smem row stride: 16 data + 4 pad (conflict-free frag reads)
#define WINLEN  160           // window arrays padded (152 used)

__global__ void __launch_bounds__(256, 2)
filter_mma_kernel(const float* __restrict__ x, float* __restrict__ out) {
    __shared__ float As_hi[128 * ASTRIDE];
    __shared__ float As_lo[128 * ASTRIDE];
    __shared__ float win_h[WINLEN];
    __shared__ float win_l[WINLEN];
    __shared__ float win_f[WINLEN];
    __shared__ float sxf16[128];

    const int tid = threadIdx.x;
    const int wid = tid >> 5;
    const int lane = tid & 31;
    const int g   = lane >> 2;    // groupID 0..7
    const int tig = lane & 3;     // thread-in-group 0..3
    const int wy = wid >> 1;      // 0..3  (l)
    const int wx = wid & 1;       // 0..1  (m)

    const int bc = blockIdx.z;
    const int l0 = blockIdx.y * 128;
    const int m0 = blockIdx.x * 128;

    // ---- x window: win[i] = x[bc][m0 + i - 8], fp32 + tf32 hi/lo ----
    if (tid < 152) {
        int gi = m0 + tid - PAD;
        float v = (gi >= 0 && gi < LL) ? x[bc * LL + gi] : 0.0f;
        float hi = to_tf32(v);
        win_f[tid] = v;
        win_h[tid] = hi;
        win_l[tid] = to_tf32(v - hi);
    }
    if (tid < 128)
        sxf16[tid] = g_xf16[bc * LL + l0 + tid];

    // ---- A fill: [128][16] gmem -> smem stride 20, float4 ----
    {
        const float4* gh = reinterpret_cast<const float4*>(g_xf_hi) + (size_t)(bc * LL + l0) * 4;
        const float4* gl = reinterpret_cast<const float4*>(g_xf_lo) + (size_t)(bc * LL + l0) * 4;
#pragma unroll
        for (int it = 0; it < 2; it++) {
            int f4 = it * 256 + tid;          // 0..511
            int row = f4 >> 2, q = f4 & 3;
            *reinterpret_cast<float4*>(&As_hi[row * ASTRIDE + q * 4]) = gh[f4];
            *reinterpret_cast<float4*>(&As_lo[row * ASTRIDE + q * 4]) = gl[f4];
        }
    }
    __syncthreads();

    // ---- accumulators: 2 mf x 8 nf x 4 ----
    float acc[2][8][4];
#pragma unroll
    for (int mf = 0; mf < 2; mf++)
#pragma unroll
        for (int nf = 0; nf < 8; nf++)
#pragma unroll
            for (int j = 0; j < 4; j++) acc[mf][nf][j] = 0.0f;

    const int rbase = wy * 32 + g;            // A fragment row base (local l)
    const int wbase = wx * 64 + g + tig;      // B hoist base: bb[j] = wp[wbase + 4j]

    // B fragment for (nf,kt): b0 = bb[2(nf+kt)], b1 = bb[2(nf+kt)+1]
    float bb[18];

#pragma unroll
    for (int p = 0; p < 3; p++) {
        // pass order: AhBh, AlBh, AhBl  (Bh regs live passes 0-1, then overwritten)
        const float* Ap = (p == 1) ? As_lo : As_hi;
        if (p == 0) {
#pragma unroll
            for (int j = 0; j < 18; j++) bb[j] = win_h[wbase + 4 * j];
        } else if (p == 2) {
#pragma unroll
            for (int j = 0; j < 18; j++) bb[j] = win_l[wbase + 4 * j];
        }
#pragma unroll
        for (int kt = 0; kt < 2; kt++) {
            const int kb = kt * 8 + tig;
#pragma unroll
            for (int mf = 0; mf < 2; mf++) {
                const float* ar = Ap + (rbase + mf * 16) * ASTRIDE + kb;
                uint32_t a0 = __float_as_uint(ar[0]);
                uint32_t a1 = __float_as_uint(ar[8 * ASTRIDE]);
                uint32_t a2 = __float_as_uint(ar[4]);
                uint32_t a3 = __float_as_uint(ar[8 * ASTRIDE + 4]);
#pragma unroll
                for (int nf = 0; nf < 8; nf++)
                    mma_tf32(acc[mf][nf],
                             a0, a1, a2, a3,
                             __float_as_uint(bb[2 * (nf + kt)]),
                             __float_as_uint(bb[2 * (nf + kt) + 1]));
            }
        }
    }

    // ---- exact tap-16 rank-1 update on the fma pipe ----
    // out[l][m] += xf16[l] * x[m+8];  x[m+8] = win_f[col_local + 16]
    {
        float a16[2][2];
#pragma unroll
        for (int mf = 0; mf < 2; mf++) {
            a16[mf][0] = sxf16[rbase + mf * 16];
            a16[mf][1] = sxf16[rbase + mf * 16 + 8];
        }
#pragma unroll
        for (int nf = 0; nf < 8; nf++) {
            int cb = wx * 64 + nf * 8 + 2 * tig + 16;
            float bf0 = win_f[cb];
            float bf1 = win_f[cb + 1];
#pragma unroll
            for (int mf = 0; mf < 2; mf++) {
                acc[mf][nf][0] += a16[mf][0] * bf0;
                acc[mf][nf][1] += a16[mf][0] * bf1;
                acc[mf][nf][2] += a16[mf][1] * bf0;
                acc[mf][nf][3] += a16[mf][1] * bf1;
            }
        }
    }

    // ---- store: fragment-layout st.v2 ----
#pragma unroll
    for (int mf = 0; mf < 2; mf++) {
        int row = l0 + rbase + mf * 16;
#pragma unroll
        for (int nf = 0; nf < 8; nf++) {
            int col = m0 + wx * 64 + nf * 8 + 2 * tig;
            float* p0 = out + (size_t)(bc * LL + row) * LL + col;
            float* p1 = p0 + (size_t)8 * LL;
            *reinterpret_cast<float2*>(p0) = make_float2(acc[mf][nf][0], acc[mf][nf][1]);
            *reinterpret_cast<float2*>(p1) = make_float2(acc[mf][nf][2], acc[mf][nf][3]);
        }
    }
}

extern "C" void kernel_launch(void* const* d_in, const int* in_sizes, int n_in,
                              void* d_out, int out_size) {
    const float* x    = (const float*)d_in[0];   // [8,2,2048]
    const float* filt = (const float*)d_in[1];   // [1,2,17,17]
    float* out = (float*)d_out;                  // [8,2,2048,2048]

    build_xf_kernel<<<(BC * LL) / 256, 256>>>(x, filt);

    dim3 grid(LL / 128, LL / 128, BC);
    filter_mma_kernel<<<grid, 256>>>(x, out);
}